// round 15
// baseline (speedup 1.0000x reference)
#include <cuda_runtime.h>
#include <cuda_bf16.h>
#include <mma.h>
#include <cstdint>
#include <math.h>

using namespace nvcuda;

#define BATCH 8192
#define UNITS 1024
#define T_STEPS 30
#define AR 12
#define RRES 64
#define GDIM 3072   // 3*UNITS

// ---------------- device scratch (static, no allocations) ----------------
__device__ float g_h[2][(size_t)BATCH * UNITS];            // ping-pong hidden state (fp32)
__device__ float g_A[77 * GDIM];                           // [W_enc; b_enc] @ W_gru
__device__ float g_gh[(size_t)BATCH * GDIM];               // h @ U_gru result
__device__ __nv_bfloat16 g_hs[3][(size_t)BATCH * UNITS];   // bf16x3 split of h
__device__ __nv_bfloat16 g_UT[3][(size_t)GDIM * UNITS];    // bf16x3 split of U_gru^T [n][k]
__device__ float g_logits[(size_t)BATCH * 76];
__device__ int   g_ia[BATCH];
__device__ int   g_ir[BATCH];

// ---------------- Threefry-2x32 (matches JAX exactly) ----------------
__host__ __device__ static inline uint32_t rotl32(uint32_t v, int d) {
    return (v << d) | (v >> (32 - d));
}
__host__ __device__ static inline void tf_round4(uint32_t& x0, uint32_t& x1,
                                                 int r0, int r1, int r2, int r3) {
    x0 += x1; x1 = rotl32(x1, r0); x1 ^= x0;
    x0 += x1; x1 = rotl32(x1, r1); x1 ^= x0;
    x0 += x1; x1 = rotl32(x1, r2); x1 ^= x0;
    x0 += x1; x1 = rotl32(x1, r3); x1 ^= x0;
}
__host__ __device__ static inline void tf2x32(uint32_t k0, uint32_t k1,
                                              uint32_t x0, uint32_t x1,
                                              uint32_t& o0, uint32_t& o1) {
    uint32_t ks2 = k0 ^ k1 ^ 0x1BD11BDAu;
    x0 += k0; x1 += k1;
    tf_round4(x0, x1, 13, 15, 26, 6);  x0 += k1;  x1 += ks2 + 1u;
    tf_round4(x0, x1, 17, 29, 16, 24); x0 += ks2; x1 += k0 + 2u;
    tf_round4(x0, x1, 13, 15, 26, 6);  x0 += k0;  x1 += k1 + 3u;
    tf_round4(x0, x1, 17, 29, 16, 24); x0 += k1;  x1 += ks2 + 4u;
    tf_round4(x0, x1, 13, 15, 26, 6);  x0 += ks2; x1 += k0 + 5u;
    o0 = x0; o1 = x1;
}
// JAX partitionable threefry bits: counter (0, e), bits = o0 ^ o1.
__device__ static inline float jax_gumbel(uint32_t k0, uint32_t k1, uint32_t e) {
    uint32_t o0, o1;
    tf2x32(k0, k1, 0u, e, o0, o1);
    uint32_t bitsv = o0 ^ o1;
    float f = __uint_as_float(0x3F800000u | (bitsv >> 9)) - 1.0f;
    float u = fmaxf(f, 1.17549435e-38f);
    return -logf(-logf(u));
}

// ---------------- kernel 0: A = [W_enc; b_enc] @ W_gru ----------------
__global__ void precompA_kernel(const float* __restrict__ W_enc,
                                const float* __restrict__ b_enc,
                                const float* __restrict__ W_gru) {
    int r = blockIdx.y;
    int c = blockIdx.x * 256 + threadIdx.x;
    const float* e = (r < 76) ? (W_enc + (size_t)r * UNITS) : b_enc;
    float acc = 0.f;
    for (int k = 0; k < UNITS; k++)
        acc = fmaf(e[k], W_gru[(size_t)k * GDIM + c], acc);
    g_A[(size_t)r * GDIM + c] = acc;
}

// ---------------- split kernels (bf16x3 error-free split) ----------------
__device__ __forceinline__ void split3(float v, __nv_bfloat16& a0, __nv_bfloat16& a1, __nv_bfloat16& a2) {
    a0 = __float2bfloat16(v);
    float r1 = v - __bfloat162float(a0);
    a1 = __float2bfloat16(r1);
    a2 = __float2bfloat16(r1 - __bfloat162float(a1));
}

__global__ void splitU_kernel(const float* __restrict__ Ug) {
    int idx = blockIdx.x * 256 + threadIdx.x;          // over GDIM*UNITS
    int k = idx / GDIM, n = idx % GDIM;                // coalesced read of Ug
    float v = Ug[idx];
    __nv_bfloat16 a0, a1, a2;
    split3(v, a0, a1, a2);
    size_t o = (size_t)n * UNITS + k;                  // transposed [n][k]
    g_UT[0][o] = a0; g_UT[1][o] = a1; g_UT[2][o] = a2;
}

__global__ void splitS_kernel(const float* __restrict__ s) {
    int idx = blockIdx.x * 256 + threadIdx.x;          // over BATCH*UNITS
    __nv_bfloat16 a0, a1, a2;
    split3(s[idx], a0, a1, a2);
    g_hs[0][idx] = a0; g_hs[1][idx] = a1; g_hs[2][idx] = a2;
}

// ---------------- kernel 1: gh = h @ U_gru via wmma bf16x3 (6 products) ----------------
// grid (GDIM/128, BATCH/128), 256 threads = 8 warps (2 m x 4 n), warp tile 64x32.
#define SROW 40                                   // padded row stride (halves)
#define SA_OFF(sp) ((sp) * 128 * SROW)
#define SB_OFF(sp) ((3 + (sp)) * 128 * SROW)
#define SM_BYTES (6 * 128 * SROW * 2)             // 61440

__global__ void __launch_bounds__(256) mma_kernel() {
    extern __shared__ __nv_bfloat16 smem[];
    int tid = threadIdx.x;
    int wid = tid >> 5;
    int warp_m = wid >> 2;       // 0..1
    int warp_n = wid & 3;        // 0..3
    int m0 = blockIdx.y * 128, n0 = blockIdx.x * 128;

    wmma::fragment<wmma::accumulator, 16, 16, 16, float> acc[4][2];
#pragma unroll
    for (int i = 0; i < 4; i++)
#pragma unroll
        for (int j = 0; j < 2; j++)
            wmma::fill_fragment(acc[i][j], 0.0f);

    const int AI[6] = {0, 0, 1, 0, 1, 2};
    const int BI[6] = {0, 1, 0, 2, 1, 0};

    int r = tid >> 1, hf = tid & 1;   // staging coords: row 0..127, 16-col half

    for (int k0 = 0; k0 < UNITS; k0 += 32) {
        // stage 3 A-splits [128x32] + 3 B-splits [128x32] bf16
#pragma unroll
        for (int sp = 0; sp < 3; sp++) {
            const uint4* ga = (const uint4*)&g_hs[sp][(size_t)(m0 + r) * UNITS + k0 + hf * 16];
            uint4* da = (uint4*)&smem[SA_OFF(sp) + r * SROW + hf * 16];
            da[0] = ga[0]; da[1] = ga[1];
            const uint4* gb = (const uint4*)&g_UT[sp][(size_t)(n0 + r) * UNITS + k0 + hf * 16];
            uint4* db = (uint4*)&smem[SB_OFF(sp) + r * SROW + hf * 16];
            db[0] = gb[0]; db[1] = gb[1];
        }
        __syncthreads();
#pragma unroll
        for (int p = 0; p < 6; p++) {
            const __nv_bfloat16* A = &smem[SA_OFF(AI[p])];
            const __nv_bfloat16* B = &smem[SB_OFF(BI[p])];
#pragma unroll
            for (int kk = 0; kk < 2; kk++) {
                wmma::fragment<wmma::matrix_a, 16, 16, 16, __nv_bfloat16, wmma::row_major> af[4];
                wmma::fragment<wmma::matrix_b, 16, 16, 16, __nv_bfloat16, wmma::col_major> bf[2];
#pragma unroll
                for (int i = 0; i < 4; i++)
                    wmma::load_matrix_sync(af[i], A + (warp_m * 64 + i * 16) * SROW + kk * 16, SROW);
#pragma unroll
                for (int j = 0; j < 2; j++)
                    wmma::load_matrix_sync(bf[j], B + (warp_n * 32 + j * 16) * SROW + kk * 16, SROW);
#pragma unroll
                for (int i = 0; i < 4; i++)
#pragma unroll
                    for (int j = 0; j < 2; j++)
                        wmma::mma_sync(acc[i][j], af[i], bf[j], acc[i][j]);
            }
        }
        __syncthreads();
    }

#pragma unroll
    for (int i = 0; i < 4; i++)
#pragma unroll
        for (int j = 0; j < 2; j++)
            wmma::store_matrix_sync(
                &g_gh[(size_t)(m0 + warp_m * 64 + i * 16) * GDIM + n0 + warp_n * 32 + j * 16],
                acc[i][j], GDIM, wmma::mem_row_major);
}

// ---------------- kernel 2: gate math + h update + bf16x3 split ----------------
__global__ void update_kernel(int t, const float* __restrict__ s, const float* __restrict__ bg) {
    int idx = blockIdx.x * 256 + threadIdx.x;   // BATCH*UNITS
    int row = idx >> 10, u = idx & 1023;
    const float* hin = (t == 0) ? s : g_h[(t - 1) & 1];
    float hv = hin[idx];
    float az = g_gh[(size_t)row * GDIM + u];
    float ar = g_gh[(size_t)row * GDIM + UNITS + u];
    float an = g_gh[(size_t)row * GDIM + 2 * UNITS + u];
    float gx0 = bg[u], gx1 = bg[UNITS + u], gx2 = bg[2 * UNITS + u];
    if (t > 0) {
        int ia = g_ia[row], ir = g_ir[row];
        gx0 += g_A[(size_t)ia * GDIM + u] + g_A[(size_t)(12 + ir) * GDIM + u] + g_A[(size_t)76 * GDIM + u];
        gx1 += g_A[(size_t)ia * GDIM + UNITS + u] + g_A[(size_t)(12 + ir) * GDIM + UNITS + u] + g_A[(size_t)76 * GDIM + UNITS + u];
        gx2 += g_A[(size_t)ia * GDIM + 2 * UNITS + u] + g_A[(size_t)(12 + ir) * GDIM + 2 * UNITS + u] + g_A[(size_t)76 * GDIM + 2 * UNITS + u];
    }
    float z = 1.f / (1.f + expf(-(gx0 + az)));
    float r = 1.f / (1.f + expf(-(gx1 + ar)));
    float n = tanhf(gx2 + r * an);
    float ho = z * hv + (1.f - z) * n;
    g_h[t & 1][idx] = ho;
    __nv_bfloat16 a0, a1, a2;
    split3(ho, a0, a1, a2);
    g_hs[0][idx] = a0; g_hs[1][idx] = a1; g_hs[2][idx] = a2;
}

// ---------------- kernel 3: logits = h @ [W_ang | W_rad] + bias ----------------
__global__ void __launch_bounds__(256) logits_kernel(int t,
        const float* __restrict__ Wa, const float* __restrict__ Wr,
        const float* __restrict__ ba, const float* __restrict__ br) {
    const float* h = g_h[t & 1];
    __shared__ __align__(16) float shHT[64][65];
    __shared__ __align__(16) float shW[64][80];
    int tid = threadIdx.x;
    int row0 = blockIdx.x * 64;
    int rr = tid & 63, cg = tid >> 6;

    float acc[20];
#pragma unroll
    for (int i = 0; i < 20; i++) acc[i] = 0.f;

    for (int k0 = 0; k0 < UNITS; k0 += 64) {
        {
            int r = tid >> 2;
            int kq = (tid & 3) * 16;
            const float* src = h + (size_t)(row0 + r) * UNITS + k0 + kq;
#pragma unroll
            for (int j = 0; j < 4; j++) {
                float4 v = *(const float4*)(src + j * 4);
                shHT[kq + j * 4 + 0][r] = v.x;
                shHT[kq + j * 4 + 1][r] = v.y;
                shHT[kq + j * 4 + 2][r] = v.z;
                shHT[kq + j * 4 + 3][r] = v.w;
            }
        }
        for (int idx = tid; idx < 64 * 80; idx += 256) {
            int k = idx / 80, c = idx % 80;
            float v = 0.f;
            if (c < 12)      v = Wa[(size_t)(k0 + k) * AR + c];
            else if (c < 76) v = Wr[(size_t)(k0 + k) * RRES + (c - 12)];
            shW[k][c] = v;
        }
        __syncthreads();
#pragma unroll 8
        for (int k = 0; k < 64; k++) {
            float hv = shHT[k][rr];
#pragma unroll
            for (int q = 0; q < 5; q++) {
                float4 w = *(const float4*)&shW[k][cg * 20 + q * 4];
                acc[q * 4 + 0] = fmaf(hv, w.x, acc[q * 4 + 0]);
                acc[q * 4 + 1] = fmaf(hv, w.y, acc[q * 4 + 1]);
                acc[q * 4 + 2] = fmaf(hv, w.z, acc[q * 4 + 2]);
                acc[q * 4 + 3] = fmaf(hv, w.w, acc[q * 4 + 3]);
            }
        }
        __syncthreads();
    }
    int row = row0 + rr;
#pragma unroll
    for (int i = 0; i < 20; i++) {
        int c = cg * 20 + i;
        if (c < 76) {
            float b = (c < 12) ? ba[c] : br[c - 12];
            g_logits[(size_t)row * 76 + c] = acc[i] + b;
        }
    }
}

// ---------------- kernel 4: sampling + softmax + output writes ----------------
__global__ void __launch_bounds__(128) sample_kernel(int t,
        unsigned ka0, unsigned ka1, unsigned kr0, unsigned kr1,
        float* __restrict__ out) {
    int row = blockIdx.x * 4 + (threadIdx.x >> 5);
    int lane = threadIdx.x & 31;
    const float* lg = &g_logits[(size_t)row * 76];
    const float NEG = -__int_as_float(0x7f800000);

    float la = NEG, ya = NEG;
    if (lane < AR) {
        la = lg[lane];
        ya = la + jax_gumbel(ka0, ka1, (unsigned)row * AR + lane);
    }
    float bv = ya; int bi = (lane < AR) ? lane : 1000;
#pragma unroll
    for (int off = 16; off; off >>= 1) {
        float ov = __shfl_xor_sync(0xffffffffu, bv, off);
        int   oi = __shfl_xor_sync(0xffffffffu, bi, off);
        if (ov > bv || (ov == bv && oi < bi)) { bv = ov; bi = oi; }
    }
    int aidx = bi;
    float m = la;
#pragma unroll
    for (int off = 16; off; off >>= 1) m = fmaxf(m, __shfl_xor_sync(0xffffffffu, m, off));
    float ex = (lane < AR) ? expf(la - m) : 0.f;
    float sm = ex;
#pragma unroll
    for (int off = 16; off; off >>= 1) sm += __shfl_xor_sync(0xffffffffu, sm, off);
    if (lane < AR) {
        size_t o = (size_t)row * (T_STEPS * AR) + (size_t)t * AR + lane;
        out[o] = (lane == aidx) ? 1.f : 0.f;
        out[(size_t)BATCH * T_STEPS * AR + o] = ex / sm;
    }

    float l0 = lg[AR + lane], l1 = lg[AR + 32 + lane];
    unsigned e0 = (unsigned)row * RRES + lane;
    float y0 = l0 + jax_gumbel(kr0, kr1, e0);
    float y1 = l1 + jax_gumbel(kr0, kr1, e0 + 32);
    float bv2; int bi2;
    if (y1 > y0) { bv2 = y1; bi2 = lane + 32; } else { bv2 = y0; bi2 = lane; }
#pragma unroll
    for (int off = 16; off; off >>= 1) {
        float ov = __shfl_xor_sync(0xffffffffu, bv2, off);
        int   oi = __shfl_xor_sync(0xffffffffu, bi2, off);
        if (ov > bv2 || (ov == bv2 && oi < bi2)) { bv2 = ov; bi2 = oi; }
    }
    int ridx = bi2;
    float m2 = fmaxf(l0, l1);
#pragma unroll
    for (int off = 16; off; off >>= 1) m2 = fmaxf(m2, __shfl_xor_sync(0xffffffffu, m2, off));
    float e0x = expf(l0 - m2), e1x = expf(l1 - m2);
    float s2 = e0x + e1x;
#pragma unroll
    for (int off = 16; off; off >>= 1) s2 += __shfl_xor_sync(0xffffffffu, s2, off);

    const size_t ROH = (size_t)BATCH * T_STEPS * AR * 2;
    const size_t RPR = ROH + (size_t)BATCH * T_STEPS * RRES;
    size_t ro = (size_t)row * (T_STEPS * RRES) + (size_t)t * RRES + lane;
    out[ROH + ro]      = (lane == ridx)      ? 1.f : 0.f;
    out[ROH + ro + 32] = (lane + 32 == ridx) ? 1.f : 0.f;
    out[RPR + ro]      = e0x / s2;
    out[RPR + ro + 32] = e1x / s2;

    if (lane == 0) { g_ia[row] = aidx; g_ir[row] = ridx; }
}

// ---------------- launcher ----------------
extern "C" void kernel_launch(void* const* d_in, const int* in_sizes, int n_in,
                              void* d_out, int out_size) {
    const float* s     = (const float*)d_in[0];
    const float* W_enc = (const float*)d_in[1];
    const float* b_enc = (const float*)d_in[2];
    const float* W_gru = (const float*)d_in[3];
    const float* U_gru = (const float*)d_in[4];
    const float* b_gru = (const float*)d_in[5];
    const float* W_ang = (const float*)d_in[6];
    const float* b_ang = (const float*)d_in[7];
    const float* W_rad = (const float*)d_in[8];
    const float* b_rad = (const float*)d_in[9];
    float* out = (float*)d_out;

    cudaFuncSetAttribute(mma_kernel, cudaFuncAttributeMaxDynamicSharedMemorySize, SM_BYTES);

    precompA_kernel<<<dim3(GDIM / 256, 77), 256>>>(W_enc, b_enc, W_gru);
    splitU_kernel<<<(GDIM * UNITS) / 256, 256>>>(U_gru);
    splitS_kernel<<<(BATCH * UNITS) / 256, 256>>>(s);

    for (int t = 0; t < T_STEPS; t++) {
        uint32_t kt0, kt1;
        tf2x32(0u, 42u, 0u, (uint32_t)t, kt0, kt1);
        uint32_t a0, a1, r0, r1;
        tf2x32(kt0, kt1, 0u, 0u, a0, a1);   // k_a
        tf2x32(kt0, kt1, 0u, 1u, r0, r1);   // k_r

        mma_kernel<<<dim3(GDIM / 128, BATCH / 128), 256, SM_BYTES>>>();
        update_kernel<<<(BATCH * UNITS) / 256, 256>>>(t, s, b_gru);
        logits_kernel<<<BATCH / 64, 256>>>(t, W_ang, W_rad, b_ang, b_rad);
        sample_kernel<<<BATCH / 4, 128>>>(t, a0, a1, r0, r1, out);
    }
}

// round 16
// speedup vs baseline: 1.1160x; 1.1160x over previous
#include <cuda_runtime.h>
#include <cuda_bf16.h>
#include <mma.h>
#include <cstdint>
#include <math.h>

using namespace nvcuda;

#define BATCH 8192
#define UNITS 1024
#define T_STEPS 30
#define AR 12
#define RRES 64
#define GDIM 3072   // 3*UNITS

// ---------------- device scratch (static, no allocations) ----------------
__device__ float g_h[2][(size_t)BATCH * UNITS];            // ping-pong hidden state (fp32)
__device__ float g_A[77 * GDIM];                           // [W_enc; b_enc] @ W_gru
__device__ float g_gh[(size_t)BATCH * GDIM];               // h @ U_gru result
__device__ __nv_bfloat16 g_hs[3][(size_t)BATCH * UNITS];   // bf16x3 split of h
__device__ __nv_bfloat16 g_UT[3][(size_t)GDIM * UNITS];    // bf16x3 split of U_gru^T [n][k]
__device__ float g_logits[(size_t)BATCH * 76];
__device__ int   g_ia[BATCH];
__device__ int   g_ir[BATCH];

// ---------------- Threefry-2x32 (matches JAX exactly) ----------------
__host__ __device__ static inline uint32_t rotl32(uint32_t v, int d) {
    return (v << d) | (v >> (32 - d));
}
__host__ __device__ static inline void tf_round4(uint32_t& x0, uint32_t& x1,
                                                 int r0, int r1, int r2, int r3) {
    x0 += x1; x1 = rotl32(x1, r0); x1 ^= x0;
    x0 += x1; x1 = rotl32(x1, r1); x1 ^= x0;
    x0 += x1; x1 = rotl32(x1, r2); x1 ^= x0;
    x0 += x1; x1 = rotl32(x1, r3); x1 ^= x0;
}
__host__ __device__ static inline void tf2x32(uint32_t k0, uint32_t k1,
                                              uint32_t x0, uint32_t x1,
                                              uint32_t& o0, uint32_t& o1) {
    uint32_t ks2 = k0 ^ k1 ^ 0x1BD11BDAu;
    x0 += k0; x1 += k1;
    tf_round4(x0, x1, 13, 15, 26, 6);  x0 += k1;  x1 += ks2 + 1u;
    tf_round4(x0, x1, 17, 29, 16, 24); x0 += ks2; x1 += k0 + 2u;
    tf_round4(x0, x1, 13, 15, 26, 6);  x0 += k0;  x1 += k1 + 3u;
    tf_round4(x0, x1, 17, 29, 16, 24); x0 += k1;  x1 += ks2 + 4u;
    tf_round4(x0, x1, 13, 15, 26, 6);  x0 += ks2; x1 += k0 + 5u;
    o0 = x0; o1 = x1;
}
// JAX partitionable threefry bits: counter (0, e), bits = o0 ^ o1.
__device__ static inline float jax_gumbel(uint32_t k0, uint32_t k1, uint32_t e) {
    uint32_t o0, o1;
    tf2x32(k0, k1, 0u, e, o0, o1);
    uint32_t bitsv = o0 ^ o1;
    float f = __uint_as_float(0x3F800000u | (bitsv >> 9)) - 1.0f;
    float u = fmaxf(f, 1.17549435e-38f);
    return -logf(-logf(u));
}

// ---------------- kernel 0: A = [W_enc; b_enc] @ W_gru ----------------
__global__ void precompA_kernel(const float* __restrict__ W_enc,
                                const float* __restrict__ b_enc,
                                const float* __restrict__ W_gru) {
    int r = blockIdx.y;
    int c = blockIdx.x * 256 + threadIdx.x;
    const float* e = (r < 76) ? (W_enc + (size_t)r * UNITS) : b_enc;
    float acc = 0.f;
    for (int k = 0; k < UNITS; k++)
        acc = fmaf(e[k], W_gru[(size_t)k * GDIM + c], acc);
    g_A[(size_t)r * GDIM + c] = acc;
}

// ---------------- split kernels (bf16x3 error-free split) ----------------
__device__ __forceinline__ void split3(float v, __nv_bfloat16& a0, __nv_bfloat16& a1, __nv_bfloat16& a2) {
    a0 = __float2bfloat16(v);
    float r1 = v - __bfloat162float(a0);
    a1 = __float2bfloat16(r1);
    a2 = __float2bfloat16(r1 - __bfloat162float(a1));
}

__global__ void splitU_kernel(const float* __restrict__ Ug) {
    int idx = blockIdx.x * 256 + threadIdx.x;          // over GDIM*UNITS
    int k = idx / GDIM, n = idx % GDIM;                // coalesced read of Ug
    float v = Ug[idx];
    __nv_bfloat16 a0, a1, a2;
    split3(v, a0, a1, a2);
    size_t o = (size_t)n * UNITS + k;                  // transposed [n][k]
    g_UT[0][o] = a0; g_UT[1][o] = a1; g_UT[2][o] = a2;
}

__global__ void splitS_kernel(const float* __restrict__ s) {
    int idx = blockIdx.x * 256 + threadIdx.x;          // over BATCH*UNITS
    __nv_bfloat16 a0, a1, a2;
    split3(s[idx], a0, a1, a2);
    g_hs[0][idx] = a0; g_hs[1][idx] = a1; g_hs[2][idx] = a2;
}

// ---------------- kernel 1: gh = h @ U_gru via wmma bf16x3 (6 products) ----------------
// grid (GDIM/128, BATCH/128), 512 threads = 16 warps (4 m x 4 n), warp tile 32x32.
// cp.async double-buffered K-chunks of 32.
#define SROW 40                                   // padded row stride (halves); 80 B rows
#define PLANE_B (128 * SROW * 2)                  // 10240 B per plane
#define BUF_B (6 * PLANE_B)                       // 61440 B per buffer
#define SM_BYTES (2 * BUF_B)                      // 122880 B

__device__ __forceinline__ uint32_t smem_u32(const void* p) {
    uint32_t a;
    asm("{ .reg .u64 t; cvta.to.shared.u64 t, %1; cvt.u32.u64 %0, t; }" : "=r"(a) : "l"(p));
    return a;
}
__device__ __forceinline__ void cp16(uint32_t dst, const void* src) {
    asm volatile("cp.async.cg.shared.global [%0], [%1], 16;" :: "r"(dst), "l"(src));
}

__global__ void __launch_bounds__(512, 1) mma_kernel() {
    extern __shared__ __nv_bfloat16 smem[];
    uint32_t sb = smem_u32(smem);
    int tid = threadIdx.x;
    int wid = tid >> 5;
    int warp_m = wid >> 2;       // 0..3
    int warp_n = wid & 3;        // 0..3
    int m0 = blockIdx.y * 128, n0 = blockIdx.x * 128;

    wmma::fragment<wmma::accumulator, 16, 16, 16, float> acc[2][2];
#pragma unroll
    for (int i = 0; i < 2; i++)
#pragma unroll
        for (int j = 0; j < 2; j++)
            wmma::fill_fragment(acc[i][j], 0.0f);

    const int AI[6] = {0, 0, 1, 0, 1, 2};
    const int BI[6] = {0, 1, 0, 2, 1, 0};

    // staging coords: each thread copies one 16B chunk per plane (6 planes)
    int r = tid >> 2, q = tid & 3;               // row 0..127, 16B chunk 0..3

    // stage(ch, buf): issue 6 cp.async per thread
#define STAGE(ch, buf) do {                                                         \
    int _k0 = (ch) * 32;                                                            \
    uint32_t _d0 = sb + (buf) * BUF_B + r * 80 + q * 16;                            \
    _Pragma("unroll")                                                               \
    for (int sp = 0; sp < 3; sp++)                                                  \
        cp16(_d0 + sp * PLANE_B, &g_hs[sp][(size_t)(m0 + r) * UNITS + _k0 + q * 8]);\
    _Pragma("unroll")                                                               \
    for (int sp = 0; sp < 3; sp++)                                                  \
        cp16(_d0 + (3 + sp) * PLANE_B, &g_UT[sp][(size_t)(n0 + r) * UNITS + _k0 + q * 8]); \
    asm volatile("cp.async.commit_group;");                                         \
} while (0)

    STAGE(0, 0);

    for (int ch = 0; ch < 32; ch++) {
        int buf = ch & 1;
        if (ch < 31) {
            STAGE(ch + 1, buf ^ 1);
            asm volatile("cp.async.wait_group 1;");
        } else {
            asm volatile("cp.async.wait_group 0;");
        }
        __syncthreads();

        const __nv_bfloat16* base = smem + buf * (BUF_B / 2);
#pragma unroll
        for (int p = 0; p < 6; p++) {
            const __nv_bfloat16* A = base + AI[p] * (PLANE_B / 2);
            const __nv_bfloat16* B = base + (3 + BI[p]) * (PLANE_B / 2);
#pragma unroll
            for (int kk = 0; kk < 2; kk++) {
                wmma::fragment<wmma::matrix_a, 16, 16, 16, __nv_bfloat16, wmma::row_major> af[2];
                wmma::fragment<wmma::matrix_b, 16, 16, 16, __nv_bfloat16, wmma::col_major> bf[2];
#pragma unroll
                for (int i = 0; i < 2; i++)
                    wmma::load_matrix_sync(af[i], A + (warp_m * 32 + i * 16) * SROW + kk * 16, SROW);
#pragma unroll
                for (int j = 0; j < 2; j++)
                    wmma::load_matrix_sync(bf[j], B + (warp_n * 32 + j * 16) * SROW + kk * 16, SROW);
#pragma unroll
                for (int i = 0; i < 2; i++)
#pragma unroll
                    for (int j = 0; j < 2; j++)
                        wmma::mma_sync(acc[i][j], af[i], bf[j], acc[i][j]);
            }
        }
        __syncthreads();
    }

#pragma unroll
    for (int i = 0; i < 2; i++)
#pragma unroll
        for (int j = 0; j < 2; j++)
            wmma::store_matrix_sync(
                &g_gh[(size_t)(m0 + warp_m * 32 + i * 16) * GDIM + n0 + warp_n * 32 + j * 16],
                acc[i][j], GDIM, wmma::mem_row_major);
}

// ---------------- kernel 2: gate math + h update + bf16x3 split ----------------
__global__ void update_kernel(int t, const float* __restrict__ s, const float* __restrict__ bg) {
    int idx = blockIdx.x * 256 + threadIdx.x;   // BATCH*UNITS
    int row = idx >> 10, u = idx & 1023;
    const float* hin = (t == 0) ? s : g_h[(t - 1) & 1];
    float hv = hin[idx];
    float az = g_gh[(size_t)row * GDIM + u];
    float ar = g_gh[(size_t)row * GDIM + UNITS + u];
    float an = g_gh[(size_t)row * GDIM + 2 * UNITS + u];
    float gx0 = bg[u], gx1 = bg[UNITS + u], gx2 = bg[2 * UNITS + u];
    if (t > 0) {
        int ia = g_ia[row], ir = g_ir[row];
        gx0 += g_A[(size_t)ia * GDIM + u] + g_A[(size_t)(12 + ir) * GDIM + u] + g_A[(size_t)76 * GDIM + u];
        gx1 += g_A[(size_t)ia * GDIM + UNITS + u] + g_A[(size_t)(12 + ir) * GDIM + UNITS + u] + g_A[(size_t)76 * GDIM + UNITS + u];
        gx2 += g_A[(size_t)ia * GDIM + 2 * UNITS + u] + g_A[(size_t)(12 + ir) * GDIM + 2 * UNITS + u] + g_A[(size_t)76 * GDIM + 2 * UNITS + u];
    }
    float z = 1.f / (1.f + expf(-(gx0 + az)));
    float r = 1.f / (1.f + expf(-(gx1 + ar)));
    float n = tanhf(gx2 + r * an);
    float ho = z * hv + (1.f - z) * n;
    g_h[t & 1][idx] = ho;
    __nv_bfloat16 a0, a1, a2;
    split3(ho, a0, a1, a2);
    g_hs[0][idx] = a0; g_hs[1][idx] = a1; g_hs[2][idx] = a2;
}

// ---------------- kernel 3: logits = h @ [W_ang | W_rad] + bias ----------------
__global__ void __launch_bounds__(256) logits_kernel(int t,
        const float* __restrict__ Wa, const float* __restrict__ Wr,
        const float* __restrict__ ba, const float* __restrict__ br) {
    const float* h = g_h[t & 1];
    __shared__ __align__(16) float shHT[64][65];
    __shared__ __align__(16) float shW[64][80];
    int tid = threadIdx.x;
    int row0 = blockIdx.x * 64;
    int rr = tid & 63, cg = tid >> 6;

    float acc[20];
#pragma unroll
    for (int i = 0; i < 20; i++) acc[i] = 0.f;

    for (int k0 = 0; k0 < UNITS; k0 += 64) {
        {
            int r = tid >> 2;
            int kq = (tid & 3) * 16;
            const float* src = h + (size_t)(row0 + r) * UNITS + k0 + kq;
#pragma unroll
            for (int j = 0; j < 4; j++) {
                float4 v = *(const float4*)(src + j * 4);
                shHT[kq + j * 4 + 0][r] = v.x;
                shHT[kq + j * 4 + 1][r] = v.y;
                shHT[kq + j * 4 + 2][r] = v.z;
                shHT[kq + j * 4 + 3][r] = v.w;
            }
        }
        for (int idx = tid; idx < 64 * 80; idx += 256) {
            int k = idx / 80, c = idx % 80;
            float v = 0.f;
            if (c < 12)      v = Wa[(size_t)(k0 + k) * AR + c];
            else if (c < 76) v = Wr[(size_t)(k0 + k) * RRES + (c - 12)];
            shW[k][c] = v;
        }
        __syncthreads();
#pragma unroll 8
        for (int k = 0; k < 64; k++) {
            float hv = shHT[k][rr];
#pragma unroll
            for (int q = 0; q < 5; q++) {
                float4 w = *(const float4*)&shW[k][cg * 20 + q * 4];
                acc[q * 4 + 0] = fmaf(hv, w.x, acc[q * 4 + 0]);
                acc[q * 4 + 1] = fmaf(hv, w.y, acc[q * 4 + 1]);
                acc[q * 4 + 2] = fmaf(hv, w.z, acc[q * 4 + 2]);
                acc[q * 4 + 3] = fmaf(hv, w.w, acc[q * 4 + 3]);
            }
        }
        __syncthreads();
    }
    int row = row0 + rr;
#pragma unroll
    for (int i = 0; i < 20; i++) {
        int c = cg * 20 + i;
        if (c < 76) {
            float b = (c < 12) ? ba[c] : br[c - 12];
            g_logits[(size_t)row * 76 + c] = acc[i] + b;
        }
    }
}

// ---------------- kernel 4: sampling + softmax + output writes ----------------
__global__ void __launch_bounds__(128) sample_kernel(int t,
        unsigned ka0, unsigned ka1, unsigned kr0, unsigned kr1,
        float* __restrict__ out) {
    int row = blockIdx.x * 4 + (threadIdx.x >> 5);
    int lane = threadIdx.x & 31;
    const float* lg = &g_logits[(size_t)row * 76];
    const float NEG = -__int_as_float(0x7f800000);

    float la = NEG, ya = NEG;
    if (lane < AR) {
        la = lg[lane];
        ya = la + jax_gumbel(ka0, ka1, (unsigned)row * AR + lane);
    }
    float bv = ya; int bi = (lane < AR) ? lane : 1000;
#pragma unroll
    for (int off = 16; off; off >>= 1) {
        float ov = __shfl_xor_sync(0xffffffffu, bv, off);
        int   oi = __shfl_xor_sync(0xffffffffu, bi, off);
        if (ov > bv || (ov == bv && oi < bi)) { bv = ov; bi = oi; }
    }
    int aidx = bi;
    float m = la;
#pragma unroll
    for (int off = 16; off; off >>= 1) m = fmaxf(m, __shfl_xor_sync(0xffffffffu, m, off));
    float ex = (lane < AR) ? expf(la - m) : 0.f;
    float sm = ex;
#pragma unroll
    for (int off = 16; off; off >>= 1) sm += __shfl_xor_sync(0xffffffffu, sm, off);
    if (lane < AR) {
        size_t o = (size_t)row * (T_STEPS * AR) + (size_t)t * AR + lane;
        out[o] = (lane == aidx) ? 1.f : 0.f;
        out[(size_t)BATCH * T_STEPS * AR + o] = ex / sm;
    }

    float l0 = lg[AR + lane], l1 = lg[AR + 32 + lane];
    unsigned e0 = (unsigned)row * RRES + lane;
    float y0 = l0 + jax_gumbel(kr0, kr1, e0);
    float y1 = l1 + jax_gumbel(kr0, kr1, e0 + 32);
    float bv2; int bi2;
    if (y1 > y0) { bv2 = y1; bi2 = lane + 32; } else { bv2 = y0; bi2 = lane; }
#pragma unroll
    for (int off = 16; off; off >>= 1) {
        float ov = __shfl_xor_sync(0xffffffffu, bv2, off);
        int   oi = __shfl_xor_sync(0xffffffffu, bi2, off);
        if (ov > bv2 || (ov == bv2 && oi < bi2)) { bv2 = ov; bi2 = oi; }
    }
    int ridx = bi2;
    float m2 = fmaxf(l0, l1);
#pragma unroll
    for (int off = 16; off; off >>= 1) m2 = fmaxf(m2, __shfl_xor_sync(0xffffffffu, m2, off));
    float e0x = expf(l0 - m2), e1x = expf(l1 - m2);
    float s2 = e0x + e1x;
#pragma unroll
    for (int off = 16; off; off >>= 1) s2 += __shfl_xor_sync(0xffffffffu, s2, off);

    const size_t ROH = (size_t)BATCH * T_STEPS * AR * 2;
    const size_t RPR = ROH + (size_t)BATCH * T_STEPS * RRES;
    size_t ro = (size_t)row * (T_STEPS * RRES) + (size_t)t * RRES + lane;
    out[ROH + ro]      = (lane == ridx)      ? 1.f : 0.f;
    out[ROH + ro + 32] = (lane + 32 == ridx) ? 1.f : 0.f;
    out[RPR + ro]      = e0x / s2;
    out[RPR + ro + 32] = e1x / s2;

    if (lane == 0) { g_ia[row] = aidx; g_ir[row] = ridx; }
}

// ---------------- launcher ----------------
extern "C" void kernel_launch(void* const* d_in, const int* in_sizes, int n_in,
                              void* d_out, int out_size) {
    const float* s     = (const float*)d_in[0];
    const float* W_enc = (const float*)d_in[1];
    const float* b_enc = (const float*)d_in[2];
    const float* W_gru = (const float*)d_in[3];
    const float* U_gru = (const float*)d_in[4];
    const float* b_gru = (const float*)d_in[5];
    const float* W_ang = (const float*)d_in[6];
    const float* b_ang = (const float*)d_in[7];
    const float* W_rad = (const float*)d_in[8];
    const float* b_rad = (const float*)d_in[9];
    float* out = (float*)d_out;

    cudaFuncSetAttribute(mma_kernel, cudaFuncAttributeMaxDynamicSharedMemorySize, SM_BYTES);

    precompA_kernel<<<dim3(GDIM / 256, 77), 256>>>(W_enc, b_enc, W_gru);
    splitU_kernel<<<(GDIM * UNITS) / 256, 256>>>(U_gru);
    splitS_kernel<<<(BATCH * UNITS) / 256, 256>>>(s);

    for (int t = 0; t < T_STEPS; t++) {
        uint32_t kt0, kt1;
        tf2x32(0u, 42u, 0u, (uint32_t)t, kt0, kt1);
        uint32_t a0, a1, r0, r1;
        tf2x32(kt0, kt1, 0u, 0u, a0, a1);   // k_a
        tf2x32(kt0, kt1, 0u, 1u, r0, r1);   // k_r

        mma_kernel<<<dim3(GDIM / 128, BATCH / 128), 512, SM_BYTES>>>();
        update_kernel<<<(BATCH * UNITS) / 256, 256>>>(t, s, b_gru);
        logits_kernel<<<BATCH / 64, 256>>>(t, W_ang, W_rad, b_ang, b_rad);
        sample_kernel<<<BATCH / 4, 128>>>(t, a0, a1, r0, r1, out);
    }
}

// round 17
// speedup vs baseline: 1.1475x; 1.0282x over previous
#include <cuda_runtime.h>
#include <cuda_bf16.h>
#include <mma.h>
#include <cstdint>
#include <math.h>

using namespace nvcuda;

#define BATCH 8192
#define UNITS 1024
#define T_STEPS 30
#define AR 12
#define RRES 64
#define GDIM 3072   // 3*UNITS

// ---------------- device scratch (static, no allocations) ----------------
__device__ float g_h[2][(size_t)BATCH * UNITS];            // ping-pong hidden state (fp32)
__device__ float g_A[77 * GDIM];                           // [W_enc; b_enc] @ W_gru
__device__ float g_gh[(size_t)BATCH * GDIM];               // h @ U_gru result
__device__ __nv_bfloat16 g_hs[3][(size_t)BATCH * UNITS];   // bf16x3 split of h
__device__ __nv_bfloat16 g_UT[3][(size_t)GDIM * UNITS];    // bf16x3 split of U_gru^T [n][k]
__device__ float g_logits[(size_t)BATCH * 76];
__device__ int   g_ia[BATCH];
__device__ int   g_ir[BATCH];

// ---------------- Threefry-2x32 (matches JAX exactly) ----------------
__host__ __device__ static inline uint32_t rotl32(uint32_t v, int d) {
    return (v << d) | (v >> (32 - d));
}
__host__ __device__ static inline void tf_round4(uint32_t& x0, uint32_t& x1,
                                                 int r0, int r1, int r2, int r3) {
    x0 += x1; x1 = rotl32(x1, r0); x1 ^= x0;
    x0 += x1; x1 = rotl32(x1, r1); x1 ^= x0;
    x0 += x1; x1 = rotl32(x1, r2); x1 ^= x0;
    x0 += x1; x1 = rotl32(x1, r3); x1 ^= x0;
}
__host__ __device__ static inline void tf2x32(uint32_t k0, uint32_t k1,
                                              uint32_t x0, uint32_t x1,
                                              uint32_t& o0, uint32_t& o1) {
    uint32_t ks2 = k0 ^ k1 ^ 0x1BD11BDAu;
    x0 += k0; x1 += k1;
    tf_round4(x0, x1, 13, 15, 26, 6);  x0 += k1;  x1 += ks2 + 1u;
    tf_round4(x0, x1, 17, 29, 16, 24); x0 += ks2; x1 += k0 + 2u;
    tf_round4(x0, x1, 13, 15, 26, 6);  x0 += k0;  x1 += k1 + 3u;
    tf_round4(x0, x1, 17, 29, 16, 24); x0 += k1;  x1 += ks2 + 4u;
    tf_round4(x0, x1, 13, 15, 26, 6);  x0 += ks2; x1 += k0 + 5u;
    o0 = x0; o1 = x1;
}
// JAX partitionable threefry bits: counter (0, e), bits = o0 ^ o1.
__device__ static inline float jax_gumbel(uint32_t k0, uint32_t k1, uint32_t e) {
    uint32_t o0, o1;
    tf2x32(k0, k1, 0u, e, o0, o1);
    uint32_t bitsv = o0 ^ o1;
    float f = __uint_as_float(0x3F800000u | (bitsv >> 9)) - 1.0f;
    float u = fmaxf(f, 1.17549435e-38f);
    return -logf(-logf(u));
}

// ---------------- kernel 0: A = [W_enc; b_enc] @ W_gru ----------------
__global__ void precompA_kernel(const float* __restrict__ W_enc,
                                const float* __restrict__ b_enc,
                                const float* __restrict__ W_gru) {
    int r = blockIdx.y;
    int c = blockIdx.x * 256 + threadIdx.x;
    const float* e = (r < 76) ? (W_enc + (size_t)r * UNITS) : b_enc;
    float acc = 0.f;
    for (int k = 0; k < UNITS; k++)
        acc = fmaf(e[k], W_gru[(size_t)k * GDIM + c], acc);
    g_A[(size_t)r * GDIM + c] = acc;
}

// ---------------- split kernels (bf16x3 error-free split) ----------------
__device__ __forceinline__ void split3(float v, __nv_bfloat16& a0, __nv_bfloat16& a1, __nv_bfloat16& a2) {
    a0 = __float2bfloat16(v);
    float r1 = v - __bfloat162float(a0);
    a1 = __float2bfloat16(r1);
    a2 = __float2bfloat16(r1 - __bfloat162float(a1));
}

__global__ void splitU_kernel(const float* __restrict__ Ug) {
    int idx = blockIdx.x * 256 + threadIdx.x;          // over GDIM*UNITS
    int k = idx / GDIM, n = idx % GDIM;                // coalesced read of Ug
    float v = Ug[idx];
    __nv_bfloat16 a0, a1, a2;
    split3(v, a0, a1, a2);
    size_t o = (size_t)n * UNITS + k;                  // transposed [n][k]
    g_UT[0][o] = a0; g_UT[1][o] = a1; g_UT[2][o] = a2;
}

__global__ void splitS_kernel(const float* __restrict__ s) {
    int idx = blockIdx.x * 256 + threadIdx.x;          // over BATCH*UNITS
    __nv_bfloat16 a0, a1, a2;
    split3(s[idx], a0, a1, a2);
    g_hs[0][idx] = a0; g_hs[1][idx] = a1; g_hs[2][idx] = a2;
}

// ---------------- kernel 1: gh = h @ U_gru via wmma bf16x3 (6 products) ----------------
// grid (GDIM/128, BATCH/128), 512 threads = 16 warps (4 m x 4 n), warp tile 32x32.
// cp.async double-buffered K-chunks of 32. A-split fragments preloaded per kk;
// per B-split: 2 loads + its mma run (B0: A0,A1,A2; B1: A0,A1; B2: A0).
#define SROW 40                                   // padded row stride (halves); 80 B rows
#define PLANE_B (128 * SROW * 2)                  // 10240 B per plane
#define BUF_B (6 * PLANE_B)                       // 61440 B per buffer
#define SM_BYTES (2 * BUF_B)                      // 122880 B

__device__ __forceinline__ uint32_t smem_u32(const void* p) {
    uint32_t a;
    asm("{ .reg .u64 t; cvta.to.shared.u64 t, %1; cvt.u32.u64 %0, t; }" : "=r"(a) : "l"(p));
    return a;
}
__device__ __forceinline__ void cp16(uint32_t dst, const void* src) {
    asm volatile("cp.async.cg.shared.global [%0], [%1], 16;" :: "r"(dst), "l"(src));
}

__global__ void __launch_bounds__(512, 1) mma_kernel() {
    extern __shared__ __nv_bfloat16 smem[];
    uint32_t sb = smem_u32(smem);
    int tid = threadIdx.x;
    int wid = tid >> 5;
    int warp_m = wid >> 2;       // 0..3
    int warp_n = wid & 3;        // 0..3
    int m0 = blockIdx.y * 128, n0 = blockIdx.x * 128;

    wmma::fragment<wmma::accumulator, 16, 16, 16, float> acc[2][2];
#pragma unroll
    for (int i = 0; i < 2; i++)
#pragma unroll
        for (int j = 0; j < 2; j++)
            wmma::fill_fragment(acc[i][j], 0.0f);

    // staging coords: each thread copies one 16B chunk per plane (6 planes)
    int r = tid >> 2, q = tid & 3;               // row 0..127, 16B chunk 0..3

#define STAGE(ch, buf) do {                                                         \
    int _k0 = (ch) * 32;                                                            \
    uint32_t _d0 = sb + (buf) * BUF_B + r * 80 + q * 16;                            \
    _Pragma("unroll")                                                               \
    for (int sp = 0; sp < 3; sp++)                                                  \
        cp16(_d0 + sp * PLANE_B, &g_hs[sp][(size_t)(m0 + r) * UNITS + _k0 + q * 8]);\
    _Pragma("unroll")                                                               \
    for (int sp = 0; sp < 3; sp++)                                                  \
        cp16(_d0 + (3 + sp) * PLANE_B, &g_UT[sp][(size_t)(n0 + r) * UNITS + _k0 + q * 8]); \
    asm volatile("cp.async.commit_group;");                                         \
} while (0)

    STAGE(0, 0);

    for (int ch = 0; ch < 32; ch++) {
        int buf = ch & 1;
        if (ch < 31) {
            STAGE(ch + 1, buf ^ 1);
            asm volatile("cp.async.wait_group 1;");
        } else {
            asm volatile("cp.async.wait_group 0;");
        }
        __syncthreads();

        const __nv_bfloat16* base = smem + buf * (BUF_B / 2);
#pragma unroll
        for (int kk = 0; kk < 2; kk++) {
            // preload all 3 A-split fragment pairs for this kk
            wmma::fragment<wmma::matrix_a, 16, 16, 16, __nv_bfloat16, wmma::row_major> af[3][2];
#pragma unroll
            for (int sp = 0; sp < 3; sp++)
#pragma unroll
                for (int i = 0; i < 2; i++)
                    wmma::load_matrix_sync(af[sp][i],
                        base + sp * (PLANE_B / 2) + (warp_m * 32 + i * 16) * SROW + kk * 16, SROW);
            // per B-split: load bf pair, run its products
#pragma unroll
            for (int sp = 0; sp < 3; sp++) {
                wmma::fragment<wmma::matrix_b, 16, 16, 16, __nv_bfloat16, wmma::col_major> bf[2];
#pragma unroll
                for (int j = 0; j < 2; j++)
                    wmma::load_matrix_sync(bf[j],
                        base + (3 + sp) * (PLANE_B / 2) + (warp_n * 32 + j * 16) * SROW + kk * 16, SROW);
#pragma unroll
                for (int sa = 0; sa < 3; sa++) {
                    if (sa + sp < 3) {   // compile-time pruned after unroll
#pragma unroll
                        for (int i = 0; i < 2; i++)
#pragma unroll
                            for (int j = 0; j < 2; j++)
                                wmma::mma_sync(acc[i][j], af[sa][i], bf[j], acc[i][j]);
                    }
                }
            }
        }
        __syncthreads();
    }

#pragma unroll
    for (int i = 0; i < 2; i++)
#pragma unroll
        for (int j = 0; j < 2; j++)
            wmma::store_matrix_sync(
                &g_gh[(size_t)(m0 + warp_m * 32 + i * 16) * GDIM + n0 + warp_n * 32 + j * 16],
                acc[i][j], GDIM, wmma::mem_row_major);
}

// ---------------- kernel 2: gate math + h update + bf16x3 split ----------------
__global__ void update_kernel(int t, const float* __restrict__ s, const float* __restrict__ bg) {
    int idx = blockIdx.x * 256 + threadIdx.x;   // BATCH*UNITS
    int row = idx >> 10, u = idx & 1023;
    const float* hin = (t == 0) ? s : g_h[(t - 1) & 1];
    float hv = hin[idx];
    float az = g_gh[(size_t)row * GDIM + u];
    float ar = g_gh[(size_t)row * GDIM + UNITS + u];
    float an = g_gh[(size_t)row * GDIM + 2 * UNITS + u];
    float gx0 = bg[u], gx1 = bg[UNITS + u], gx2 = bg[2 * UNITS + u];
    if (t > 0) {
        int ia = g_ia[row], ir = g_ir[row];
        gx0 += g_A[(size_t)ia * GDIM + u] + g_A[(size_t)(12 + ir) * GDIM + u] + g_A[(size_t)76 * GDIM + u];
        gx1 += g_A[(size_t)ia * GDIM + UNITS + u] + g_A[(size_t)(12 + ir) * GDIM + UNITS + u] + g_A[(size_t)76 * GDIM + UNITS + u];
        gx2 += g_A[(size_t)ia * GDIM + 2 * UNITS + u] + g_A[(size_t)(12 + ir) * GDIM + 2 * UNITS + u] + g_A[(size_t)76 * GDIM + 2 * UNITS + u];
    }
    float z = 1.f / (1.f + expf(-(gx0 + az)));
    float r = 1.f / (1.f + expf(-(gx1 + ar)));
    float n = tanhf(gx2 + r * an);
    float ho = z * hv + (1.f - z) * n;
    g_h[t & 1][idx] = ho;
    __nv_bfloat16 a0, a1, a2;
    split3(ho, a0, a1, a2);
    g_hs[0][idx] = a0; g_hs[1][idx] = a1; g_hs[2][idx] = a2;
}

// ---------------- kernel 3: logits = h @ [W_ang | W_rad] + bias ----------------
__global__ void __launch_bounds__(256) logits_kernel(int t,
        const float* __restrict__ Wa, const float* __restrict__ Wr,
        const float* __restrict__ ba, const float* __restrict__ br) {
    const float* h = g_h[t & 1];
    __shared__ __align__(16) float shHT[64][65];
    __shared__ __align__(16) float shW[64][80];
    int tid = threadIdx.x;
    int row0 = blockIdx.x * 64;
    int rr = tid & 63, cg = tid >> 6;

    float acc[20];
#pragma unroll
    for (int i = 0; i < 20; i++) acc[i] = 0.f;

    for (int k0 = 0; k0 < UNITS; k0 += 64) {
        {
            int r = tid >> 2;
            int kq = (tid & 3) * 16;
            const float* src = h + (size_t)(row0 + r) * UNITS + k0 + kq;
#pragma unroll
            for (int j = 0; j < 4; j++) {
                float4 v = *(const float4*)(src + j * 4);
                shHT[kq + j * 4 + 0][r] = v.x;
                shHT[kq + j * 4 + 1][r] = v.y;
                shHT[kq + j * 4 + 2][r] = v.z;
                shHT[kq + j * 4 + 3][r] = v.w;
            }
        }
        for (int idx = tid; idx < 64 * 80; idx += 256) {
            int k = idx / 80, c = idx % 80;
            float v = 0.f;
            if (c < 12)      v = Wa[(size_t)(k0 + k) * AR + c];
            else if (c < 76) v = Wr[(size_t)(k0 + k) * RRES + (c - 12)];
            shW[k][c] = v;
        }
        __syncthreads();
#pragma unroll 8
        for (int k = 0; k < 64; k++) {
            float hv = shHT[k][rr];
#pragma unroll
            for (int q = 0; q < 5; q++) {
                float4 w = *(const float4*)&shW[k][cg * 20 + q * 4];
                acc[q * 4 + 0] = fmaf(hv, w.x, acc[q * 4 + 0]);
                acc[q * 4 + 1] = fmaf(hv, w.y, acc[q * 4 + 1]);
                acc[q * 4 + 2] = fmaf(hv, w.z, acc[q * 4 + 2]);
                acc[q * 4 + 3] = fmaf(hv, w.w, acc[q * 4 + 3]);
            }
        }
        __syncthreads();
    }
    int row = row0 + rr;
#pragma unroll
    for (int i = 0; i < 20; i++) {
        int c = cg * 20 + i;
        if (c < 76) {
            float b = (c < 12) ? ba[c] : br[c - 12];
            g_logits[(size_t)row * 76 + c] = acc[i] + b;
        }
    }
}

// ---------------- kernel 4: sampling + softmax + output writes ----------------
__global__ void __launch_bounds__(128) sample_kernel(int t,
        unsigned ka0, unsigned ka1, unsigned kr0, unsigned kr1,
        float* __restrict__ out) {
    int row = blockIdx.x * 4 + (threadIdx.x >> 5);
    int lane = threadIdx.x & 31;
    const float* lg = &g_logits[(size_t)row * 76];
    const float NEG = -__int_as_float(0x7f800000);

    float la = NEG, ya = NEG;
    if (lane < AR) {
        la = lg[lane];
        ya = la + jax_gumbel(ka0, ka1, (unsigned)row * AR + lane);
    }
    float bv = ya; int bi = (lane < AR) ? lane : 1000;
#pragma unroll
    for (int off = 16; off; off >>= 1) {
        float ov = __shfl_xor_sync(0xffffffffu, bv, off);
        int   oi = __shfl_xor_sync(0xffffffffu, bi, off);
        if (ov > bv || (ov == bv && oi < bi)) { bv = ov; bi = oi; }
    }
    int aidx = bi;
    float m = la;
#pragma unroll
    for (int off = 16; off; off >>= 1) m = fmaxf(m, __shfl_xor_sync(0xffffffffu, m, off));
    float ex = (lane < AR) ? expf(la - m) : 0.f;
    float sm = ex;
#pragma unroll
    for (int off = 16; off; off >>= 1) sm += __shfl_xor_sync(0xffffffffu, sm, off);
    if (lane < AR) {
        size_t o = (size_t)row * (T_STEPS * AR) + (size_t)t * AR + lane;
        out[o] = (lane == aidx) ? 1.f : 0.f;
        out[(size_t)BATCH * T_STEPS * AR + o] = ex / sm;
    }

    float l0 = lg[AR + lane], l1 = lg[AR + 32 + lane];
    unsigned e0 = (unsigned)row * RRES + lane;
    float y0 = l0 + jax_gumbel(kr0, kr1, e0);
    float y1 = l1 + jax_gumbel(kr0, kr1, e0 + 32);
    float bv2; int bi2;
    if (y1 > y0) { bv2 = y1; bi2 = lane + 32; } else { bv2 = y0; bi2 = lane; }
#pragma unroll
    for (int off = 16; off; off >>= 1) {
        float ov = __shfl_xor_sync(0xffffffffu, bv2, off);
        int   oi = __shfl_xor_sync(0xffffffffu, bi2, off);
        if (ov > bv2 || (ov == bv2 && oi < bi2)) { bv2 = ov; bi2 = oi; }
    }
    int ridx = bi2;
    float m2 = fmaxf(l0, l1);
#pragma unroll
    for (int off = 16; off; off >>= 1) m2 = fmaxf(m2, __shfl_xor_sync(0xffffffffu, m2, off));
    float e0x = expf(l0 - m2), e1x = expf(l1 - m2);
    float s2 = e0x + e1x;
#pragma unroll
    for (int off = 16; off; off >>= 1) s2 += __shfl_xor_sync(0xffffffffu, s2, off);

    const size_t ROH = (size_t)BATCH * T_STEPS * AR * 2;
    const size_t RPR = ROH + (size_t)BATCH * T_STEPS * RRES;
    size_t ro = (size_t)row * (T_STEPS * RRES) + (size_t)t * RRES + lane;
    out[ROH + ro]      = (lane == ridx)      ? 1.f : 0.f;
    out[ROH + ro + 32] = (lane + 32 == ridx) ? 1.f : 0.f;
    out[RPR + ro]      = e0x / s2;
    out[RPR + ro + 32] = e1x / s2;

    if (lane == 0) { g_ia[row] = aidx; g_ir[row] = ridx; }
}

// ---------------- launcher ----------------
extern "C" void kernel_launch(void* const* d_in, const int* in_sizes, int n_in,
                              void* d_out, int out_size) {
    const float* s     = (const float*)d_in[0];
    const float* W_enc = (const float*)d_in[1];
    const float* b_enc = (const float*)d_in[2];
    const float* W_gru = (const float*)d_in[3];
    const float* U_gru = (const float*)d_in[4];
    const float* b_gru = (const float*)d_in[5];
    const float* W_ang = (const float*)d_in[6];
    const float* b_ang = (const float*)d_in[7];
    const float* W_rad = (const float*)d_in[8];
    const float* b_rad = (const float*)d_in[9];
    float* out = (float*)d_out;

    cudaFuncSetAttribute(mma_kernel, cudaFuncAttributeMaxDynamicSharedMemorySize, SM_BYTES);

    precompA_kernel<<<dim3(GDIM / 256, 77), 256>>>(W_enc, b_enc, W_gru);
    splitU_kernel<<<(GDIM * UNITS) / 256, 256>>>(U_gru);
    splitS_kernel<<<(BATCH * UNITS) / 256, 256>>>(s);

    for (int t = 0; t < T_STEPS; t++) {
        uint32_t kt0, kt1;
        tf2x32(0u, 42u, 0u, (uint32_t)t, kt0, kt1);
        uint32_t a0, a1, r0, r1;
        tf2x32(kt0, kt1, 0u, 0u, a0, a1);   // k_a
        tf2x32(kt0, kt1, 0u, 1u, r0, r1);   // k_r

        mma_kernel<<<dim3(GDIM / 128, BATCH / 128), 512, SM_BYTES>>>();
        update_kernel<<<(BATCH * UNITS) / 256, 256>>>(t, s, b_gru);
        logits_kernel<<<BATCH / 64, 256>>>(t, W_ang, W_rad, b_ang, b_rad);
        sample_kernel<<<BATCH / 4, 128>>>(t, a0, a1, r0, r1, out);
    }
}